// round 4
// baseline (speedup 1.0000x reference)
#include <cuda_runtime.h>
#include <cuda_bf16.h>
#include <cstdint>

// Problem constants
#define BB 4
#define TT 2048
#define DD 1024
#define HH 16
#define HD 64
// M = B*T = 8192 rows

// Scratch (device globals: no allocation allowed)
__device__ float g_qkv[(size_t)BB * TT * 3 * DD];   // [8192, 3072]
__device__ float g_y[(size_t)BB * TT * DD];          // [8192, 1024]

// ---------------------------------------------------------------------------
// Fast exp2: p = 2^y for y <= 0 (clamped at -126). 5-FFMA Taylor, |f|<=0.5.
// ---------------------------------------------------------------------------
__device__ __forceinline__ float fast_exp2(float y) {
    y = fmaxf(y, -126.0f);
    int ei = __float2int_rn(y);
    float f = y - (float)ei;
    float p = 0.0013333558146428443f;
    p = fmaf(p, f, 0.009618129107628477f);
    p = fmaf(p, f, 0.05550410866482158f);
    p = fmaf(p, f, 0.2402265069591007f);
    p = fmaf(p, f, 0.6931471805599453f);
    p = fmaf(p, f, 1.0f);
    return p * __int_as_float((ei + 127) << 23);
}

// ---------------------------------------------------------------------------
// SGEMM: C[M,N] = A[M,K] @ B[K,N], row-major, fp32.
// 128x128 block tile, BK=16, 8x8 per thread, 256 threads.
// M % 128 == 0, N % 128 == 0, K % 16 == 0 (all true here).
// ---------------------------------------------------------------------------
#define BM 128
#define BN 128
#define BK 16

__global__ __launch_bounds__(256, 2)
void sgemm_kernel(const float* __restrict__ A, const float* __restrict__ Bm,
                  float* __restrict__ C, int M, int K, int N) {
    __shared__ float As[BK][BM];   // transposed A tile
    __shared__ float Bs[BK][BN];

    const int tid = threadIdx.x;
    const int row0 = blockIdx.y * BM;
    const int col0 = blockIdx.x * BN;

    const int tx = tid & 15;        // 0..15 -> N direction
    const int ty = tid >> 4;        // 0..15 -> M direction

    float acc[8][8];
#pragma unroll
    for (int i = 0; i < 8; i++)
#pragma unroll
        for (int j = 0; j < 8; j++) acc[i][j] = 0.0f;

    for (int kk = 0; kk < K; kk += BK) {
        // Load A tile (128x16): 512 float4, 2 per thread
#pragma unroll
        for (int it = 0; it < 2; it++) {
            int idx = tid + it * 256;
            int ar = idx >> 2;          // 0..127
            int ac4 = idx & 3;          // 0..3
            float4 av = *reinterpret_cast<const float4*>(
                &A[(size_t)(row0 + ar) * K + kk + ac4 * 4]);
            As[ac4 * 4 + 0][ar] = av.x;
            As[ac4 * 4 + 1][ar] = av.y;
            As[ac4 * 4 + 2][ar] = av.z;
            As[ac4 * 4 + 3][ar] = av.w;
        }
        // Load B tile (16x128): 512 float4, 2 per thread
#pragma unroll
        for (int it = 0; it < 2; it++) {
            int idx = tid + it * 256;
            int br = idx >> 5;          // 0..15
            int bc4 = idx & 31;         // 0..31
            float4 bv = *reinterpret_cast<const float4*>(
                &Bm[(size_t)(kk + br) * N + col0 + bc4 * 4]);
            *reinterpret_cast<float4*>(&Bs[br][bc4 * 4]) = bv;
        }
        __syncthreads();

#pragma unroll
        for (int k = 0; k < BK; k++) {
            float a[8], b[8];
            float4 a0 = *reinterpret_cast<const float4*>(&As[k][ty * 8]);
            float4 a1 = *reinterpret_cast<const float4*>(&As[k][ty * 8 + 4]);
            float4 b0 = *reinterpret_cast<const float4*>(&Bs[k][tx * 8]);
            float4 b1 = *reinterpret_cast<const float4*>(&Bs[k][tx * 8 + 4]);
            a[0]=a0.x; a[1]=a0.y; a[2]=a0.z; a[3]=a0.w;
            a[4]=a1.x; a[5]=a1.y; a[6]=a1.z; a[7]=a1.w;
            b[0]=b0.x; b[1]=b0.y; b[2]=b0.z; b[3]=b0.w;
            b[4]=b1.x; b[5]=b1.y; b[6]=b1.z; b[7]=b1.w;
#pragma unroll
            for (int i = 0; i < 8; i++)
#pragma unroll
                for (int j = 0; j < 8; j++)
                    acc[i][j] = fmaf(a[i], b[j], acc[i][j]);
        }
        __syncthreads();
    }

    // Epilogue
#pragma unroll
    for (int i = 0; i < 8; i++) {
        float4 o0 = make_float4(acc[i][0], acc[i][1], acc[i][2], acc[i][3]);
        float4 o1 = make_float4(acc[i][4], acc[i][5], acc[i][6], acc[i][7]);
        float* crow = &C[(size_t)(row0 + ty * 8 + i) * N + col0 + tx * 8];
        *reinterpret_cast<float4*>(crow) = o0;
        *reinterpret_cast<float4*>(crow + 4) = o1;
    }
}

// ---------------------------------------------------------------------------
// Flash attention (fp32, causal). One block = 128 query rows of one (b,h).
// 128 threads; thread t owns query row q0+t. K/V tiles of 64 keys in smem,
// per-thread q[64] and acc[64] in registers, S row staged in smem (pad 65).
// Online softmax in base 2 with polynomial exp2.
// qkv layout: [B*T, 3*D] rows; q at col h*64, k at D + h*64, v at 2D + h*64.
// Output y: [B*T, D].
// ---------------------------------------------------------------------------
#define FA_BM 128
#define FA_BN 64

__global__ __launch_bounds__(128, 1)
void flash_attn_kernel(const float* __restrict__ qkv, float* __restrict__ y) {
    extern __shared__ float sm[];
    float* Ks = sm;                        // [64][64]
    float* Vs = sm + FA_BN * HD;           // [64][64]
    float* Ss = Vs + FA_BN * HD;           // [128][65]

    const int tid = threadIdx.x;
    const int q0 = blockIdx.x * FA_BM;
    const int bh = blockIdx.y;
    const int b = bh / HH;
    const int h = bh % HH;
    const int qi = q0 + tid;               // global query index for this thread
    const int row3 = 3 * DD;

    // Load q row, pre-scaled by (1/sqrt(hd)) * log2(e)
    const float scale2 = 0.125f * 1.4426950408889634f;
    float qreg[HD];
    {
        const float4* qp = reinterpret_cast<const float4*>(
            qkv + (size_t)(b * TT + qi) * row3 + h * HD);
#pragma unroll
        for (int d4 = 0; d4 < HD / 4; d4++) {
            float4 v = qp[d4];
            qreg[4 * d4 + 0] = v.x * scale2;
            qreg[4 * d4 + 1] = v.y * scale2;
            qreg[4 * d4 + 2] = v.z * scale2;
            qreg[4 * d4 + 3] = v.w * scale2;
        }
    }

    float m2 = -1e30f, l = 0.0f;
    float accv[HD];
#pragma unroll
    for (int d = 0; d < HD; d++) accv[d] = 0.0f;

    const int ntiles = q0 / FA_BN + 2;     // tiles with kv0 < q0 + FA_BM
    float* srow = Ss + tid * (FA_BN + 1);

    for (int t = 0; t < ntiles; t++) {
        const int kv0 = t * FA_BN;
        __syncthreads();
        // Load K and V tiles: 64 rows x 64 floats = 1024 float4 each, 8/thread
        {
            const float* kbase = qkv + (size_t)(b * TT + kv0) * row3 + DD + h * HD;
            const float* vbase = kbase + DD;
#pragma unroll
            for (int i = 0; i < 8; i++) {
                int idx = tid + i * 128;
                int r = idx >> 4;          // 0..63
                int c4 = idx & 15;         // 0..15
                float4 kv4 = *reinterpret_cast<const float4*>(kbase + (size_t)r * row3 + c4 * 4);
                *reinterpret_cast<float4*>(&Ks[r * HD + c4 * 4]) = kv4;
                float4 vv4 = *reinterpret_cast<const float4*>(vbase + (size_t)r * row3 + c4 * 4);
                *reinterpret_cast<float4*>(&Vs[r * HD + c4 * 4]) = vv4;
            }
        }
        __syncthreads();

        // Phase A: scores for this thread's q row vs 64 keys; track tile max
        float mtile = -1e30f;
        const bool full = (kv0 + FA_BN - 1) <= qi;   // no masking needed
#pragma unroll 4
        for (int j = 0; j < FA_BN; j++) {
            const float4* kr = reinterpret_cast<const float4*>(Ks + j * HD);
            float s0 = 0.f, s1 = 0.f, s2 = 0.f, s3 = 0.f;
#pragma unroll
            for (int d4 = 0; d4 < HD / 4; d4++) {
                float4 kk = kr[d4];
                s0 = fmaf(qreg[4 * d4 + 0], kk.x, s0);
                s1 = fmaf(qreg[4 * d4 + 1], kk.y, s1);
                s2 = fmaf(qreg[4 * d4 + 2], kk.z, s2);
                s3 = fmaf(qreg[4 * d4 + 3], kk.w, s3);
            }
            float s = (s0 + s1) + (s2 + s3);
            if (!full && (kv0 + j > qi)) s = -1e30f;
            srow[j] = s;
            mtile = fmaxf(mtile, s);
        }

        float m2new = fmaxf(m2, mtile);
        float corr = fast_exp2(m2 - m2new);
        m2 = m2new;
        l *= corr;
#pragma unroll
        for (int d = 0; d < HD; d++) accv[d] *= corr;

        // Phase B: p = exp2(s - m2), accumulate p*V
        for (int j = 0; j < FA_BN; j++) {
            float p = fast_exp2(srow[j] - m2);
            l += p;
            const float4* vr = reinterpret_cast<const float4*>(Vs + j * HD);
#pragma unroll
            for (int d4 = 0; d4 < HD / 4; d4++) {
                float4 vv = vr[d4];
                accv[4 * d4 + 0] = fmaf(p, vv.x, accv[4 * d4 + 0]);
                accv[4 * d4 + 1] = fmaf(p, vv.y, accv[4 * d4 + 1]);
                accv[4 * d4 + 2] = fmaf(p, vv.z, accv[4 * d4 + 2]);
                accv[4 * d4 + 3] = fmaf(p, vv.w, accv[4 * d4 + 3]);
            }
        }
    }

    // Epilogue: normalize and store to y [B*T, D]
    const float inv = 1.0f / l;
    float4* yp = reinterpret_cast<float4*>(y + (size_t)(b * TT + qi) * DD + h * HD);
#pragma unroll
    for (int d4 = 0; d4 < HD / 4; d4++) {
        float4 o;
        o.x = accv[4 * d4 + 0] * inv;
        o.y = accv[4 * d4 + 1] * inv;
        o.z = accv[4 * d4 + 2] * inv;
        o.w = accv[4 * d4 + 3] * inv;
        yp[d4] = o;
    }
}

// ---------------------------------------------------------------------------
// kernel_launch
// ---------------------------------------------------------------------------
extern "C" void kernel_launch(void* const* d_in, const int* in_sizes, int n_in,
                              void* d_out, int out_size) {
    const float* x  = (const float*)d_in[0];   // [4,2048,1024]
    const float* Wa = (const float*)d_in[1];   // [1024,3072]
    const float* Wp = (const float*)d_in[2];   // [1024,1024]
    float* out = (float*)d_out;                // [4,2048,1024]

    float* qkv_ptr = nullptr;
    float* y_ptr = nullptr;
    cudaGetSymbolAddress((void**)&qkv_ptr, g_qkv);
    cudaGetSymbolAddress((void**)&y_ptr, g_y);

    const int M = BB * TT;                     // 8192

    // 1) QKV GEMM: [8192,1024] @ [1024,3072] -> g_qkv
    {
        dim3 grid(3 * DD / BN, M / BM);
        sgemm_kernel<<<grid, 256>>>(x, Wa, qkv_ptr, M, DD, 3 * DD);
    }

    // 2) Flash attention -> g_y
    {
        const int smem_bytes = (2 * FA_BN * HD + FA_BM * (FA_BN + 1)) * (int)sizeof(float);
        cudaFuncSetAttribute(flash_attn_kernel,
                             cudaFuncAttributeMaxDynamicSharedMemorySize, smem_bytes);
        dim3 grid(TT / FA_BM, BB * HH);
        flash_attn_kernel<<<grid, 128, smem_bytes>>>(qkv_ptr, y_ptr);
    }

    // 3) Proj GEMM: [8192,1024] @ [1024,1024] -> out
    {
        dim3 grid(DD / BN, M / BM);
        sgemm_kernel<<<grid, 256>>>(y_ptr, Wp, out, M, DD, DD);
    }
}

// round 8
// speedup vs baseline: 1.3525x; 1.3525x over previous
#include <cuda_runtime.h>
#include <cuda_bf16.h>
#include <cstdint>

// Problem constants
#define BB 4
#define TT 2048
#define DD 1024
#define HH 16
#define HD 64
// M = B*T = 8192 rows

// Scratch (device globals: no allocation allowed)
__device__ float g_qkv[(size_t)BB * TT * 3 * DD];   // [8192, 3072]
__device__ float g_y[(size_t)BB * TT * DD];          // [8192, 1024]

// ---------------------------------------------------------------------------
// tf32 helpers (portable PTX: works on compute_103 target, no 'a' feature)
// ---------------------------------------------------------------------------
__device__ __forceinline__ uint32_t to_tf32(float x) {
    uint32_t r;
    asm("cvt.rna.tf32.f32 %0, %1;" : "=r"(r) : "f"(x));
    return r;
}

// mma.sync m16n8k8 tf32: D(16x8,f32) += A(16x8,tf32) * B(8x8,tf32)
__device__ __forceinline__ void mma_tf32(float* d,
                                         uint32_t a0, uint32_t a1, uint32_t a2, uint32_t a3,
                                         uint32_t b0, uint32_t b1) {
    asm volatile(
        "mma.sync.aligned.m16n8k8.row.col.f32.tf32.tf32.f32 "
        "{%0,%1,%2,%3}, {%4,%5,%6,%7}, {%8,%9}, {%0,%1,%2,%3};"
        : "+f"(d[0]), "+f"(d[1]), "+f"(d[2]), "+f"(d[3])
        : "r"(a0), "r"(a1), "r"(a2), "r"(a3), "r"(b0), "r"(b1));
}

// ===========================================================================
// Tensor-core GEMM via mma.sync tf32: C[M,N] = A[M,K] @ B[K,N], row-major fp32.
// CTA 128x128, BK=16, 256 threads (8 warps, 4x2), warp tile 32x64.
//
// Smem tiles are [row][16] floats (16B-aligned rows; LDS.128-safe).
// k is PERMUTED: k' = (k&3)*4 + (k>>2), so the float4 at group g=tig holds
// k = {tig, tig+4, tig+8, tig+12} = exactly the A/B fragment elements for
// both k-steps of BK=16.
// Bank conflicts are avoided via XOR swizzle on the group index:
//     stored group = logical group ^ ((row >> 1) & 3)
// (verified conflict-free for frag LDS.128, A STS.32, B STS.128).
// Requires M%128==0, N%128==0, K%16==0.
// ===========================================================================
#define GM 128
#define GN 128
#define GK 16

__global__ __launch_bounds__(256, 1)
void mma_gemm(const float* __restrict__ A, const float* __restrict__ Bm,
              float* __restrict__ C, int M, int K, int N) {
    __shared__ float As[2][GM * GK];   // [128][16]
    __shared__ float Bs[2][GN * GK];   // [128][16]

    const int tid = threadIdx.x;
    const int lane = tid & 31;
    const int wid = tid >> 5;
    const int wm = wid >> 1;        // 0..3 (M direction, 32 rows each)
    const int wn = wid & 1;         // 0..1 (N direction, 64 cols each)
    const int row0 = blockIdx.y * GM;
    const int col0 = blockIdx.x * GN;

    const int gid = lane >> 2;      // groupID 0..7
    const int tig = lane & 3;       // threadID_in_group 0..3

    float acc[2][8][4];
#pragma unroll
    for (int mf = 0; mf < 2; mf++)
#pragma unroll
        for (int nf = 0; nf < 8; nf++)
#pragma unroll
            for (int i = 0; i < 4; i++) acc[mf][nf][i] = 0.0f;

    float4 ra[2];
    float rb[2][4];

    // ---- gmem load of stage kk0 into registers ----
    auto ldg = [&](int kk0) {
        // A: 2 x LDG.128; idx -> (row ar, k-group at4)
#pragma unroll
        for (int it = 0; it < 2; it++) {
            int idx = tid + it * 256;
            int ar = idx >> 2;                 // 0..127
            int at4 = idx & 3;                 // 0..3
            ra[it] = *reinterpret_cast<const float4*>(
                &A[(size_t)(row0 + ar) * K + kk0 + at4 * 4]);
        }
        // B: per thread one n, one k'-group c; loads k = c, c+4, c+8, c+12
        // (coalesced across warp in n).
#pragma unroll
        for (int it = 0; it < 2; it++) {
            int idx = tid + it * 256;
            int n = idx & 127;
            int c = idx >> 7;                  // 0..3
            const float* bp = &Bm[(size_t)(kk0 + c) * N + col0 + n];
#pragma unroll
            for (int jj = 0; jj < 4; jj++)
                rb[it][jj] = bp[(size_t)jj * 4 * N];
        }
    };

    // ---- store registers to smem stage s (tf32 convert + k-permute + swizzle) --
    auto sts = [&](int s) {
#pragma unroll
        for (int it = 0; it < 2; it++) {
            int idx = tid + it * 256;
            int ar = idx >> 2;
            int at4 = idx & 3;
            int sw = (ar >> 1) & 3;
            float* dst = &As[s][ar * GK + at4];
            // element jj of float4 has k = at4*4 + jj -> k' = jj*4 + at4
            // (group jj, offset at4); stored group = jj ^ sw
            dst[((0 ^ sw) << 2)] = __uint_as_float(to_tf32(ra[it].x));
            dst[((1 ^ sw) << 2)] = __uint_as_float(to_tf32(ra[it].y));
            dst[((2 ^ sw) << 2)] = __uint_as_float(to_tf32(ra[it].z));
            dst[((3 ^ sw) << 2)] = __uint_as_float(to_tf32(ra[it].w));
        }
#pragma unroll
        for (int it = 0; it < 2; it++) {
            int idx = tid + it * 256;
            int n = idx & 127;
            int c = idx >> 7;
            int sw = (n >> 1) & 3;
            uint4 t;
            t.x = to_tf32(rb[it][0]); t.y = to_tf32(rb[it][1]);
            t.z = to_tf32(rb[it][2]); t.w = to_tf32(rb[it][3]);
            *reinterpret_cast<uint4*>(&Bs[s][n * GK + ((c ^ sw) << 2)]) = t;
        }
    };

    // ---- compute one BK=16 stage from smem stage s ----
    auto compute = [&](int s) {
        float4 av0[2], av1[2], bv[8];
#pragma unroll
        for (int mf = 0; mf < 2; mf++) {
            int r = wm * 32 + mf * 16 + gid;
            int r2 = r + 8;
            av0[mf] = *reinterpret_cast<const float4*>(
                &As[s][r * GK + ((tig ^ ((r >> 1) & 3)) << 2)]);
            av1[mf] = *reinterpret_cast<const float4*>(
                &As[s][r2 * GK + ((tig ^ ((r2 >> 1) & 3)) << 2)]);
        }
#pragma unroll
        for (int nf = 0; nf < 8; nf++) {
            int n = wn * 64 + nf * 8 + gid;
            bv[nf] = *reinterpret_cast<const float4*>(
                &Bs[s][n * GK + ((tig ^ ((n >> 1) & 3)) << 2)]);
        }
        // k-step 0 uses .x/.y, k-step 1 uses .z/.w
#pragma unroll
        for (int mf = 0; mf < 2; mf++) {
            uint32_t a0 = __float_as_uint(av0[mf].x), a1 = __float_as_uint(av1[mf].x);
            uint32_t a2 = __float_as_uint(av0[mf].y), a3 = __float_as_uint(av1[mf].y);
#pragma unroll
            for (int nf = 0; nf < 8; nf++)
                mma_tf32(acc[mf][nf], a0, a1, a2, a3,
                         __float_as_uint(bv[nf].x), __float_as_uint(bv[nf].y));
        }
#pragma unroll
        for (int mf = 0; mf < 2; mf++) {
            uint32_t a0 = __float_as_uint(av0[mf].z), a1 = __float_as_uint(av1[mf].z);
            uint32_t a2 = __float_as_uint(av0[mf].w), a3 = __float_as_uint(av1[mf].w);
#pragma unroll
            for (int nf = 0; nf < 8; nf++)
                mma_tf32(acc[mf][nf], a0, a1, a2, a3,
                         __float_as_uint(bv[nf].z), __float_as_uint(bv[nf].w));
        }
    };

    const int nk = K / GK;
    ldg(0);
    sts(0);
    __syncthreads();

    for (int kk = 0; kk < nk; kk++) {
        int s = kk & 1;
        if (kk + 1 < nk) ldg((kk + 1) * GK);
        compute(s);
        if (kk + 1 < nk) {
            sts(s ^ 1);
            __syncthreads();
        }
    }

    // Epilogue: c0,c1 = (r, 2*tig), (r, 2*tig+1); c2,c3 = same at r+8
#pragma unroll
    for (int mf = 0; mf < 2; mf++) {
#pragma unroll
        for (int nf = 0; nf < 8; nf++) {
            int r = row0 + wm * 32 + mf * 16 + gid;
            int c = col0 + wn * 64 + nf * 8 + tig * 2;
            float2 lo = make_float2(acc[mf][nf][0], acc[mf][nf][1]);
            float2 hi = make_float2(acc[mf][nf][2], acc[mf][nf][3]);
            *reinterpret_cast<float2*>(&C[(size_t)r * N + c]) = lo;
            *reinterpret_cast<float2*>(&C[(size_t)(r + 8) * N + c]) = hi;
        }
    }
}

// ---------------------------------------------------------------------------
// Fast exp2: p = 2^y for y <= 0 (clamped at -126). 5-FFMA Taylor, |f|<=0.5.
// ---------------------------------------------------------------------------
__device__ __forceinline__ float fast_exp2(float y) {
    y = fmaxf(y, -126.0f);
    int ei = __float2int_rn(y);
    float f = y - (float)ei;
    float p = 0.0013333558146428443f;
    p = fmaf(p, f, 0.009618129107628477f);
    p = fmaf(p, f, 0.05550410866482158f);
    p = fmaf(p, f, 0.2402265069591007f);
    p = fmaf(p, f, 0.6931471805599453f);
    p = fmaf(p, f, 1.0f);
    return p * __int_as_float((ei + 127) << 23);
}

// ---------------------------------------------------------------------------
// Flash attention (fp32, causal). One block = 128 query rows of one (b,h).
// ---------------------------------------------------------------------------
#define FA_BM 128
#define FA_BN 64

__global__ __launch_bounds__(128, 1)
void flash_attn_kernel(const float* __restrict__ qkv, float* __restrict__ y) {
    extern __shared__ float sm[];
    float* Ks = sm;                        // [64][64]
    float* Vs = sm + FA_BN * HD;           // [64][64]
    float* Ss = Vs + FA_BN * HD;           // [128][65]

    const int tid = threadIdx.x;
    const int q0 = blockIdx.x * FA_BM;
    const int bh = blockIdx.y;
    const int b = bh / HH;
    const int h = bh % HH;
    const int qi = q0 + tid;
    const int row3 = 3 * DD;

    const float scale2 = 0.125f * 1.4426950408889634f;
    float qreg[HD];
    {
        const float4* qp = reinterpret_cast<const float4*>(
            qkv + (size_t)(b * TT + qi) * row3 + h * HD);
#pragma unroll
        for (int d4 = 0; d4 < HD / 4; d4++) {
            float4 v = qp[d4];
            qreg[4 * d4 + 0] = v.x * scale2;
            qreg[4 * d4 + 1] = v.y * scale2;
            qreg[4 * d4 + 2] = v.z * scale2;
            qreg[4 * d4 + 3] = v.w * scale2;
        }
    }

    float m2 = -1e30f, l = 0.0f;
    float accv[HD];
#pragma unroll
    for (int d = 0; d < HD; d++) accv[d] = 0.0f;

    const int ntiles = q0 / FA_BN + 2;
    float* srow = Ss + tid * (FA_BN + 1);

    for (int t = 0; t < ntiles; t++) {
        const int kv0 = t * FA_BN;
        __syncthreads();
        {
            const float* kbase = qkv + (size_t)(b * TT + kv0) * row3 + DD + h * HD;
            const float* vbase = kbase + DD;
#pragma unroll
            for (int i = 0; i < 8; i++) {
                int idx = tid + i * 128;
                int r = idx >> 4;
                int c4 = idx & 15;
                float4 kv4 = *reinterpret_cast<const float4*>(kbase + (size_t)r * row3 + c4 * 4);
                *reinterpret_cast<float4*>(&Ks[r * HD + c4 * 4]) = kv4;
                float4 vv4 = *reinterpret_cast<const float4*>(vbase + (size_t)r * row3 + c4 * 4);
                *reinterpret_cast<float4*>(&Vs[r * HD + c4 * 4]) = vv4;
            }
        }
        __syncthreads();

        float mtile = -1e30f;
        const bool full = (kv0 + FA_BN - 1) <= qi;
#pragma unroll 4
        for (int j = 0; j < FA_BN; j++) {
            const float4* kr = reinterpret_cast<const float4*>(Ks + j * HD);
            float s0 = 0.f, s1 = 0.f, s2 = 0.f, s3 = 0.f;
#pragma unroll
            for (int d4 = 0; d4 < HD / 4; d4++) {
                float4 kk = kr[d4];
                s0 = fmaf(qreg[4 * d4 + 0], kk.x, s0);
                s1 = fmaf(qreg[4 * d4 + 1], kk.y, s1);
                s2 = fmaf(qreg[4 * d4 + 2], kk.z, s2);
                s3 = fmaf(qreg[4 * d4 + 3], kk.w, s3);
            }
            float s = (s0 + s1) + (s2 + s3);
            if (!full && (kv0 + j > qi)) s = -1e30f;
            srow[j] = s;
            mtile = fmaxf(mtile, s);
        }

        float m2new = fmaxf(m2, mtile);
        float corr = fast_exp2(m2 - m2new);
        m2 = m2new;
        l *= corr;
#pragma unroll
        for (int d = 0; d < HD; d++) accv[d] *= corr;

        for (int j = 0; j < FA_BN; j++) {
            float p = fast_exp2(srow[j] - m2);
            l += p;
            const float4* vr = reinterpret_cast<const float4*>(Vs + j * HD);
#pragma unroll
            for (int d4 = 0; d4 < HD / 4; d4++) {
                float4 vv = vr[d4];
                accv[4 * d4 + 0] = fmaf(p, vv.x, accv[4 * d4 + 0]);
                accv[4 * d4 + 1] = fmaf(p, vv.y, accv[4 * d4 + 1]);
                accv[4 * d4 + 2] = fmaf(p, vv.z, accv[4 * d4 + 2]);
                accv[4 * d4 + 3] = fmaf(p, vv.w, accv[4 * d4 + 3]);
            }
        }
    }

    const float inv = 1.0f / l;
    float4* yp = reinterpret_cast<float4*>(y + (size_t)(b * TT + qi) * DD + h * HD);
#pragma unroll
    for (int d4 = 0; d4 < HD / 4; d4++) {
        float4 o;
        o.x = accv[4 * d4 + 0] * inv;
        o.y = accv[4 * d4 + 1] * inv;
        o.z = accv[4 * d4 + 2] * inv;
        o.w = accv[4 * d4 + 3] * inv;
        yp[d4] = o;
    }
}

// ---------------------------------------------------------------------------
// kernel_launch
// ---------------------------------------------------------------------------
extern "C" void kernel_launch(void* const* d_in, const int* in_sizes, int n_in,
                              void* d_out, int out_size) {
    const float* x  = (const float*)d_in[0];   // [4,2048,1024]
    const float* Wa = (const float*)d_in[1];   // [1024,3072]
    const float* Wp = (const float*)d_in[2];   // [1024,1024]
    float* out = (float*)d_out;                // [4,2048,1024]

    float* qkv_ptr = nullptr;
    float* y_ptr = nullptr;
    cudaGetSymbolAddress((void**)&qkv_ptr, g_qkv);
    cudaGetSymbolAddress((void**)&y_ptr, g_y);

    const int M = BB * TT;                     // 8192

    // 1) QKV GEMM: [8192,1024] @ [1024,3072] -> g_qkv   (mma.sync tf32)
    {
        dim3 grid(3 * DD / GN, M / GM);
        mma_gemm<<<grid, 256>>>(x, Wa, qkv_ptr, M, DD, 3 * DD);
    }

    // 2) Flash attention -> g_y
    {
        const int smem_bytes = (2 * FA_BN * HD + FA_BM * (FA_BN + 1)) * (int)sizeof(float);
        cudaFuncSetAttribute(flash_attn_kernel,
                             cudaFuncAttributeMaxDynamicSharedMemorySize, smem_bytes);
        dim3 grid(TT / FA_BM, BB * HH);
        flash_attn_kernel<<<grid, 128, smem_bytes>>>(qkv_ptr, y_ptr);
    }

    // 3) Proj GEMM: [8192,1024] @ [1024,1024] -> out    (mma.sync tf32)
    {
        dim3 grid(DD / GN, M / GM);
        mma_gemm<<<grid, 256>>>(y_ptr, Wp, out, M, DD, DD);
    }
}

// round 9
// speedup vs baseline: 2.6911x; 1.9897x over previous
#include <cuda_runtime.h>
#include <cuda_bf16.h>
#include <cstdint>

// Problem constants
#define BB 4
#define TT 2048
#define DD 1024
#define HH 16
#define HD 64
// M = B*T = 8192 rows

// Scratch (device globals: no allocation allowed)
__device__ float g_qkv[(size_t)BB * TT * 3 * DD];   // [8192, 3072]
__device__ float g_y[(size_t)BB * TT * DD];          // [8192, 1024]

// ---------------------------------------------------------------------------
// tf32 helpers (portable PTX: works on compute_103 target, no 'a' feature)
// ---------------------------------------------------------------------------
__device__ __forceinline__ uint32_t to_tf32(float x) {
    uint32_t r;
    asm("cvt.rna.tf32.f32 %0, %1;" : "=r"(r) : "f"(x));
    return r;
}

// mma.sync m16n8k8 tf32: D(16x8,f32) += A(16x8,tf32) * B(8x8,tf32)
__device__ __forceinline__ void mma_tf32(float* d,
                                         uint32_t a0, uint32_t a1, uint32_t a2, uint32_t a3,
                                         uint32_t b0, uint32_t b1) {
    asm volatile(
        "mma.sync.aligned.m16n8k8.row.col.f32.tf32.tf32.f32 "
        "{%0,%1,%2,%3}, {%4,%5,%6,%7}, {%8,%9}, {%0,%1,%2,%3};"
        : "+f"(d[0]), "+f"(d[1]), "+f"(d[2]), "+f"(d[3])
        : "r"(a0), "r"(a1), "r"(a2), "r"(a3), "r"(b0), "r"(b1));
}

// ---------------------------------------------------------------------------
// Fast exp2: p = 2^y for y <= 0 (clamped at -126). 5-FFMA Taylor, |f|<=0.5.
// ---------------------------------------------------------------------------
__device__ __forceinline__ float fast_exp2(float y) {
    y = fmaxf(y, -126.0f);
    int ei = __float2int_rn(y);
    float f = y - (float)ei;
    float p = 0.0013333558146428443f;
    p = fmaf(p, f, 0.009618129107628477f);
    p = fmaf(p, f, 0.05550410866482158f);
    p = fmaf(p, f, 0.2402265069591007f);
    p = fmaf(p, f, 0.6931471805599453f);
    p = fmaf(p, f, 1.0f);
    return p * __int_as_float((ei + 127) << 23);
}

// ===========================================================================
// Tensor-core GEMM via mma.sync tf32 (unchanged from round 8; passes).
// ===========================================================================
#define GM 128
#define GN 128
#define GK 16

__global__ __launch_bounds__(256, 1)
void mma_gemm(const float* __restrict__ A, const float* __restrict__ Bm,
              float* __restrict__ C, int M, int K, int N) {
    __shared__ float As[2][GM * GK];   // [128][16]
    __shared__ float Bs[2][GN * GK];   // [128][16]

    const int tid = threadIdx.x;
    const int lane = tid & 31;
    const int wid = tid >> 5;
    const int wm = wid >> 1;
    const int wn = wid & 1;
    const int row0 = blockIdx.y * GM;
    const int col0 = blockIdx.x * GN;

    const int gid = lane >> 2;
    const int tig = lane & 3;

    float acc[2][8][4];
#pragma unroll
    for (int mf = 0; mf < 2; mf++)
#pragma unroll
        for (int nf = 0; nf < 8; nf++)
#pragma unroll
            for (int i = 0; i < 4; i++) acc[mf][nf][i] = 0.0f;

    float4 ra[2];
    float rb[2][4];

    auto ldg = [&](int kk0) {
#pragma unroll
        for (int it = 0; it < 2; it++) {
            int idx = tid + it * 256;
            int ar = idx >> 2;
            int at4 = idx & 3;
            ra[it] = *reinterpret_cast<const float4*>(
                &A[(size_t)(row0 + ar) * K + kk0 + at4 * 4]);
        }
#pragma unroll
        for (int it = 0; it < 2; it++) {
            int idx = tid + it * 256;
            int n = idx & 127;
            int c = idx >> 7;
            const float* bp = &Bm[(size_t)(kk0 + c) * N + col0 + n];
#pragma unroll
            for (int jj = 0; jj < 4; jj++)
                rb[it][jj] = bp[(size_t)jj * 4 * N];
        }
    };

    auto sts = [&](int s) {
#pragma unroll
        for (int it = 0; it < 2; it++) {
            int idx = tid + it * 256;
            int ar = idx >> 2;
            int at4 = idx & 3;
            int sw = (ar >> 1) & 3;
            float* dst = &As[s][ar * GK + at4];
            dst[((0 ^ sw) << 2)] = __uint_as_float(to_tf32(ra[it].x));
            dst[((1 ^ sw) << 2)] = __uint_as_float(to_tf32(ra[it].y));
            dst[((2 ^ sw) << 2)] = __uint_as_float(to_tf32(ra[it].z));
            dst[((3 ^ sw) << 2)] = __uint_as_float(to_tf32(ra[it].w));
        }
#pragma unroll
        for (int it = 0; it < 2; it++) {
            int idx = tid + it * 256;
            int n = idx & 127;
            int c = idx >> 7;
            int sw = (n >> 1) & 3;
            uint4 t;
            t.x = to_tf32(rb[it][0]); t.y = to_tf32(rb[it][1]);
            t.z = to_tf32(rb[it][2]); t.w = to_tf32(rb[it][3]);
            *reinterpret_cast<uint4*>(&Bs[s][n * GK + ((c ^ sw) << 2)]) = t;
        }
    };

    auto compute = [&](int s) {
        float4 av0[2], av1[2], bv[8];
#pragma unroll
        for (int mf = 0; mf < 2; mf++) {
            int r = wm * 32 + mf * 16 + gid;
            int r2 = r + 8;
            av0[mf] = *reinterpret_cast<const float4*>(
                &As[s][r * GK + ((tig ^ ((r >> 1) & 3)) << 2)]);
            av1[mf] = *reinterpret_cast<const float4*>(
                &As[s][r2 * GK + ((tig ^ ((r2 >> 1) & 3)) << 2)]);
        }
#pragma unroll
        for (int nf = 0; nf < 8; nf++) {
            int n = wn * 64 + nf * 8 + gid;
            bv[nf] = *reinterpret_cast<const float4*>(
                &Bs[s][n * GK + ((tig ^ ((n >> 1) & 3)) << 2)]);
        }
#pragma unroll
        for (int mf = 0; mf < 2; mf++) {
            uint32_t a0 = __float_as_uint(av0[mf].x), a1 = __float_as_uint(av1[mf].x);
            uint32_t a2 = __float_as_uint(av0[mf].y), a3 = __float_as_uint(av1[mf].y);
#pragma unroll
            for (int nf = 0; nf < 8; nf++)
                mma_tf32(acc[mf][nf], a0, a1, a2, a3,
                         __float_as_uint(bv[nf].x), __float_as_uint(bv[nf].y));
        }
#pragma unroll
        for (int mf = 0; mf < 2; mf++) {
            uint32_t a0 = __float_as_uint(av0[mf].z), a1 = __float_as_uint(av1[mf].z);
            uint32_t a2 = __float_as_uint(av0[mf].w), a3 = __float_as_uint(av1[mf].w);
#pragma unroll
            for (int nf = 0; nf < 8; nf++)
                mma_tf32(acc[mf][nf], a0, a1, a2, a3,
                         __float_as_uint(bv[nf].z), __float_as_uint(bv[nf].w));
        }
    };

    const int nk = K / GK;
    ldg(0);
    sts(0);
    __syncthreads();

    for (int kk = 0; kk < nk; kk++) {
        int s = kk & 1;
        if (kk + 1 < nk) ldg((kk + 1) * GK);
        compute(s);
        if (kk + 1 < nk) {
            sts(s ^ 1);
            __syncthreads();
        }
    }

#pragma unroll
    for (int mf = 0; mf < 2; mf++) {
#pragma unroll
        for (int nf = 0; nf < 8; nf++) {
            int r = row0 + wm * 32 + mf * 16 + gid;
            int c = col0 + wn * 64 + nf * 8 + tig * 2;
            float2 lo = make_float2(acc[mf][nf][0], acc[mf][nf][1]);
            float2 hi = make_float2(acc[mf][nf][2], acc[mf][nf][3]);
            *reinterpret_cast<float2*>(&C[(size_t)r * N + c]) = lo;
            *reinterpret_cast<float2*>(&C[(size_t)(r + 8) * N + c]) = hi;
        }
    }
}

// ===========================================================================
// Flash attention via mma.sync tf32 (causal).
// CTA: 256 threads (8 warps) = 128 q-rows of one (b,h); warp w owns rows
// 16w..16w+15. Q fragments persistent in regs, split 2xTF32 (q_hi + q_lo).
// K/V tiles (64 keys) in smem, stride 68 floats (all fragment LDS patterns
// bank-conflict-free: (4*gid+tig)%32 unique). P goes through smem (tf32-rna
// rounded) to convert accum layout -> A-operand layout. Online softmax in
// base-2, per-row stats via 4-lane shuffles. K/V double-buffered via
// register staging. Heavy q-blocks scheduled first (reversed blockIdx.y).
// ===========================================================================
#define ATS 68   // smem row stride (floats)

__global__ __launch_bounds__(256, 1)
void flash_attn_mma(const float* __restrict__ qkv, float* __restrict__ y) {
    extern __shared__ float sm[];
    float* Ks = sm;                  // [64][68]
    float* Vs = sm + 64 * ATS;       // [64][68]
    float* Ps = sm + 2 * 64 * ATS;   // [128][68] (also Q staging)

    const int tid = threadIdx.x;
    const int lane = tid & 31;
    const int w = tid >> 5;          // 0..7
    const int gid = lane >> 2;       // 0..7
    const int tig = lane & 3;        // 0..3
    const int bh = blockIdx.x;
    const int b = bh >> 4;
    const int h = bh & 15;
    const int q0 = (15 - (int)blockIdx.y) * 128;   // heavy blocks first
    const int row3 = 3 * DD;

    const float* qkv_b = qkv + (size_t)(b * TT) * row3;
    const float* qgm = qkv_b + h * HD;
    const float* kgm = qkv_b + DD + h * HD;
    const float* vgm = qkv_b + 2 * DD + h * HD;

    // ---- Stage Q tile into Ps, then build per-warp Q fragments (2x split) --
#pragma unroll
    for (int i = 0; i < 8; i++) {
        int idx = tid + i * 256;
        int r = idx >> 4, c4 = idx & 15;
        float4 v = *reinterpret_cast<const float4*>(
            qgm + (size_t)(q0 + r) * row3 + c4 * 4);
        *reinterpret_cast<float4*>(Ps + r * ATS + c4 * 4) = v;
    }
    __syncthreads();

    const float scale2 = 0.125f * 1.4426950408889634f;
    uint32_t qhi[8][4], qlo[8][4];
    {
        const int r0 = w * 16 + gid;
#pragma unroll
        for (int c = 0; c < 8; c++) {
            float v0 = Ps[r0 * ATS + 8 * c + tig] * scale2;          // a0
            float v1 = Ps[(r0 + 8) * ATS + 8 * c + tig] * scale2;    // a1
            float v2 = Ps[r0 * ATS + 8 * c + tig + 4] * scale2;      // a2
            float v3 = Ps[(r0 + 8) * ATS + 8 * c + tig + 4] * scale2;// a3
            qhi[c][0] = to_tf32(v0); qlo[c][0] = to_tf32(v0 - __uint_as_float(qhi[c][0]));
            qhi[c][1] = to_tf32(v1); qlo[c][1] = to_tf32(v1 - __uint_as_float(qhi[c][1]));
            qhi[c][2] = to_tf32(v2); qlo[c][2] = to_tf32(v2 - __uint_as_float(qhi[c][2]));
            qhi[c][3] = to_tf32(v3); qlo[c][3] = to_tf32(v3 - __uint_as_float(qhi[c][3]));
        }
    }
    __syncthreads();

    float yacc[8][4];
#pragma unroll
    for (int j = 0; j < 8; j++)
#pragma unroll
        for (int e = 0; e < 4; e++) yacc[j][e] = 0.0f;
    float m0 = -1e30f, m1 = -1e30f, l0 = 0.0f, l1 = 0.0f;

    const int ntiles = q0 / 64 + 2;
    float4 kreg[4], vreg[4];

    // gmem -> regs for tile tn
    auto ldg_kv = [&](int tn) {
        int kv0 = tn * 64;
#pragma unroll
        for (int i = 0; i < 4; i++) {
            int idx = tid + i * 256;
            int r = idx >> 4, c4 = idx & 15;
            kreg[i] = *reinterpret_cast<const float4*>(
                kgm + (size_t)(kv0 + r) * row3 + c4 * 4);
            vreg[i] = *reinterpret_cast<const float4*>(
                vgm + (size_t)(kv0 + r) * row3 + c4 * 4);
        }
    };
    // regs -> smem (tf32 rna rounding)
    auto sts_kv = [&]() {
#pragma unroll
        for (int i = 0; i < 4; i++) {
            int idx = tid + i * 256;
            int r = idx >> 4, c4 = idx & 15;
            uint4 tk, tv;
            tk.x = to_tf32(kreg[i].x); tk.y = to_tf32(kreg[i].y);
            tk.z = to_tf32(kreg[i].z); tk.w = to_tf32(kreg[i].w);
            tv.x = to_tf32(vreg[i].x); tv.y = to_tf32(vreg[i].y);
            tv.z = to_tf32(vreg[i].z); tv.w = to_tf32(vreg[i].w);
            *reinterpret_cast<uint4*>(Ks + r * ATS + c4 * 4) = tk;
            *reinterpret_cast<uint4*>(Vs + r * ATS + c4 * 4) = tv;
        }
    };

    ldg_kv(0);
    sts_kv();
    __syncthreads();

    const int pr0 = (w * 16 + gid) * ATS;

    for (int t = 0; t < ntiles; t++) {
        const int kv0 = t * 64;
        if (t + 1 < ntiles) ldg_kv(t + 1);

        // warp fully masked for this tile? (all its rows < kv0)
        const bool active = (kv0 <= q0 + w * 16 + 15);
        if (active) {
            // ---- QK^T (2xTF32: q_hi*K + q_lo*K) ----
            float sacc[8][4];
#pragma unroll
            for (int j = 0; j < 8; j++)
#pragma unroll
                for (int e = 0; e < 4; e++) sacc[j][e] = 0.0f;
#pragma unroll
            for (int j = 0; j < 8; j++) {
                const int kr = (8 * j + gid) * ATS;
#pragma unroll
                for (int c = 0; c < 8; c++) {
                    uint32_t b0 = __float_as_uint(Ks[kr + 8 * c + tig]);
                    uint32_t b1 = __float_as_uint(Ks[kr + 8 * c + tig + 4]);
                    mma_tf32(sacc[j], qhi[c][0], qhi[c][1], qhi[c][2], qhi[c][3], b0, b1);
                    mma_tf32(sacc[j], qlo[c][0], qlo[c][1], qlo[c][2], qlo[c][3], b0, b1);
                }
            }

            // ---- causal mask (only last two tiles) ----
            if (t >= ntiles - 2) {
                const int r0g = q0 + w * 16 + gid;
#pragma unroll
                for (int j = 0; j < 8; j++) {
                    int col = kv0 + 8 * j + 2 * tig;
                    if (col > r0g)         sacc[j][0] = -1e30f;
                    if (col + 1 > r0g)     sacc[j][1] = -1e30f;
                    if (col > r0g + 8)     sacc[j][2] = -1e30f;
                    if (col + 1 > r0g + 8) sacc[j][3] = -1e30f;
                }
            }

            // ---- online softmax ----
            float mt0 = -1e30f, mt1 = -1e30f;
#pragma unroll
            for (int j = 0; j < 8; j++) {
                mt0 = fmaxf(mt0, fmaxf(sacc[j][0], sacc[j][1]));
                mt1 = fmaxf(mt1, fmaxf(sacc[j][2], sacc[j][3]));
            }
            mt0 = fmaxf(mt0, __shfl_xor_sync(0xffffffffu, mt0, 1));
            mt0 = fmaxf(mt0, __shfl_xor_sync(0xffffffffu, mt0, 2));
            mt1 = fmaxf(mt1, __shfl_xor_sync(0xffffffffu, mt1, 1));
            mt1 = fmaxf(mt1, __shfl_xor_sync(0xffffffffu, mt1, 2));

            float mn0 = fmaxf(m0, mt0), mn1 = fmaxf(m1, mt1);
            float cr0 = fast_exp2(m0 - mn0), cr1 = fast_exp2(m1 - mn1);
            m0 = mn0; m1 = mn1;
#pragma unroll
            for (int j = 0; j < 8; j++) {
                yacc[j][0] *= cr0; yacc[j][1] *= cr0;
                yacc[j][2] *= cr1; yacc[j][3] *= cr1;
            }

            float rs0 = 0.0f, rs1 = 0.0f;
#pragma unroll
            for (int j = 0; j < 8; j++) {
                float p0 = fast_exp2(sacc[j][0] - m0);
                float p1 = fast_exp2(sacc[j][1] - m0);
                float p2 = fast_exp2(sacc[j][2] - m1);
                float p3 = fast_exp2(sacc[j][3] - m1);
                rs0 += p0 + p1; rs1 += p2 + p3;
                float2 lo, hi;
                lo.x = __uint_as_float(to_tf32(p0)); lo.y = __uint_as_float(to_tf32(p1));
                hi.x = __uint_as_float(to_tf32(p2)); hi.y = __uint_as_float(to_tf32(p3));
                *reinterpret_cast<float2*>(Ps + pr0 + 8 * j + 2 * tig) = lo;
                *reinterpret_cast<float2*>(Ps + pr0 + 8 * ATS + 8 * j + 2 * tig) = hi;
            }
            rs0 += __shfl_xor_sync(0xffffffffu, rs0, 1);
            rs0 += __shfl_xor_sync(0xffffffffu, rs0, 2);
            rs1 += __shfl_xor_sync(0xffffffffu, rs1, 1);
            rs1 += __shfl_xor_sync(0xffffffffu, rs1, 2);
            l0 = l0 * cr0 + rs0;
            l1 = l1 * cr1 + rs1;

            __syncwarp();

            // ---- P @ V ----
#pragma unroll
            for (int c = 0; c < 8; c++) {
                uint32_t a0 = __float_as_uint(Ps[pr0 + 8 * c + tig]);
                uint32_t a1 = __float_as_uint(Ps[pr0 + 8 * ATS + 8 * c + tig]);
                uint32_t a2 = __float_as_uint(Ps[pr0 + 8 * c + tig + 4]);
                uint32_t a3 = __float_as_uint(Ps[pr0 + 8 * ATS + 8 * c + tig + 4]);
                const int vr = (8 * c + tig) * ATS;
#pragma unroll
                for (int j = 0; j < 8; j++) {
                    uint32_t b0 = __float_as_uint(Vs[vr + 8 * j + gid]);
                    uint32_t b1 = __float_as_uint(Vs[vr + 4 * ATS + 8 * j + gid]);
                    mma_tf32(yacc[j], a0, a1, a2, a3, b0, b1);
                }
            }
        }

        __syncthreads();                 // all warps done with Ks/Vs
        if (t + 1 < ntiles) {
            sts_kv();
            __syncthreads();             // tiles visible before next compute
        }
    }

    // ---- epilogue: normalize, store ----
    const float inv0 = 1.0f / l0;
    const float inv1 = 1.0f / l1;
    const int r0 = q0 + w * 16 + gid;
#pragma unroll
    for (int j = 0; j < 8; j++) {
        int col = h * HD + 8 * j + 2 * tig;
        float2 lo = make_float2(yacc[j][0] * inv0, yacc[j][1] * inv0);
        float2 hi = make_float2(yacc[j][2] * inv1, yacc[j][3] * inv1);
        *reinterpret_cast<float2*>(y + (size_t)(b * TT + r0) * DD + col) = lo;
        *reinterpret_cast<float2*>(y + (size_t)(b * TT + r0 + 8) * DD + col) = hi;
    }
}

// ---------------------------------------------------------------------------
// kernel_launch
// ---------------------------------------------------------------------------
extern "C" void kernel_launch(void* const* d_in, const int* in_sizes, int n_in,
                              void* d_out, int out_size) {
    const float* x  = (const float*)d_in[0];   // [4,2048,1024]
    const float* Wa = (const float*)d_in[1];   // [1024,3072]
    const float* Wp = (const float*)d_in[2];   // [1024,1024]
    float* out = (float*)d_out;                // [4,2048,1024]

    float* qkv_ptr = nullptr;
    float* y_ptr = nullptr;
    cudaGetSymbolAddress((void**)&qkv_ptr, g_qkv);
    cudaGetSymbolAddress((void**)&y_ptr, g_y);

    const int M = BB * TT;                     // 8192

    // 1) QKV GEMM: [8192,1024] @ [1024,3072] -> g_qkv   (mma.sync tf32)
    {
        dim3 grid(3 * DD / GN, M / GM);
        mma_gemm<<<grid, 256>>>(x, Wa, qkv_ptr, M, DD, 3 * DD);
    }

    // 2) Flash attention (mma.sync tf32) -> g_y
    {
        const int smem_bytes = (2 * 64 * ATS + 128 * ATS) * (int)sizeof(float); // 69632
        cudaFuncSetAttribute(flash_attn_mma,
                             cudaFuncAttributeMaxDynamicSharedMemorySize, smem_bytes);
        dim3 grid(BB * HH, TT / 128);
        flash_attn_mma<<<grid, 256, smem_bytes>>>(qkv_ptr, y_ptr);
    }

    // 3) Proj GEMM: [8192,1024] @ [1024,1024] -> out    (mma.sync tf32)
    {
        dim3 grid(DD / GN, M / GM);
        mma_gemm<<<grid, 256>>>(y_ptr, Wp, out, M, DD, DD);
    }
}

// round 11
// speedup vs baseline: 2.9988x; 1.1143x over previous
#include <cuda_runtime.h>
#include <cuda_bf16.h>
#include <cstdint>

// Problem constants
#define BB 4
#define TT 2048
#define DD 1024
#define HH 16
#define HD 64
// M = B*T = 8192 rows

// Scratch (device globals: no allocation allowed)
__device__ float g_qkv[(size_t)BB * TT * 3 * DD];   // [8192, 3072]
__device__ float g_y[(size_t)BB * TT * DD];          // [8192, 1024]

// ---------------------------------------------------------------------------
// tf32 helpers (portable PTX: works on compute_103 target, no 'a' feature)
// ---------------------------------------------------------------------------
__device__ __forceinline__ uint32_t to_tf32(float x) {
    uint32_t r;
    asm("cvt.rna.tf32.f32 %0, %1;" : "=r"(r) : "f"(x));
    return r;
}

// mma.sync m16n8k8 tf32: D(16x8,f32) += A(16x8,tf32) * B(8x8,tf32)
__device__ __forceinline__ void mma_tf32(float* d,
                                         uint32_t a0, uint32_t a1, uint32_t a2, uint32_t a3,
                                         uint32_t b0, uint32_t b1) {
    asm volatile(
        "mma.sync.aligned.m16n8k8.row.col.f32.tf32.tf32.f32 "
        "{%0,%1,%2,%3}, {%4,%5,%6,%7}, {%8,%9}, {%0,%1,%2,%3};"
        : "+f"(d[0]), "+f"(d[1]), "+f"(d[2]), "+f"(d[3])
        : "r"(a0), "r"(a1), "r"(a2), "r"(a3), "r"(b0), "r"(b1));
}

// ---------------------------------------------------------------------------
// Fast exp2: p = 2^y for y <= 0 (clamped at -126). 5-FFMA Taylor, |f|<=0.5.
// ---------------------------------------------------------------------------
__device__ __forceinline__ float fast_exp2(float y) {
    y = fmaxf(y, -126.0f);
    int ei = __float2int_rn(y);
    float f = y - (float)ei;
    float p = 0.0013333558146428443f;
    p = fmaf(p, f, 0.009618129107628477f);
    p = fmaf(p, f, 0.05550410866482158f);
    p = fmaf(p, f, 0.2402265069591007f);
    p = fmaf(p, f, 0.6931471805599453f);
    p = fmaf(p, f, 1.0f);
    return p * __int_as_float((ei + 127) << 23);
}

// ===========================================================================
// Tensor-core GEMM via mma.sync tf32: C[M,N] = A[M,1024] @ B[1024,N].
// CTA tile 128x256, 512 threads (16 warps, 4x4), warp tile 32x64, BK=16.
// K hardcoded to 1024. Streamed B fragments keep regs <= 128 so all 16
// warps stay resident. All smem fragment addresses are base+immediate
// (swizzle group proven invariant across mf/nf steps).
// Requires M%128==0, N%256==0.
// ===========================================================================
#define GEMM_K 1024
#define GKS 16
#define NSTAGE (GEMM_K / GKS)   // 64
#define GEMM_SMEM ((2 * 128 * 16 + 2 * 256 * 16) * 4)   // 49152 bytes

__global__ __launch_bounds__(512, 1)
void mma_gemm(const float* __restrict__ A, const float* __restrict__ Bm,
              float* __restrict__ C, int N) {
    extern __shared__ float smg[];
    float* const As0 = smg;                    // [128*16]
    float* const As1 = smg + 128 * 16;
    float* const Bs0 = smg + 2 * 128 * 16;     // [256*16]
    float* const Bs1 = Bs0 + 256 * 16;

    const int tid = threadIdx.x;
    const int lane = tid & 31;
    const int wid = tid >> 5;       // 0..15
    const int wm = wid >> 2;        // 0..3 (M, 32 rows each)
    const int wn = wid & 3;         // 0..3 (N, 64 cols each)
    const int row0 = blockIdx.y * 128;
    const int col0 = blockIdx.x * 256;
    const int gid = lane >> 2;      // 0..7
    const int tig = lane & 3;       // 0..3

    // ---- ldg pointers (advance by immediate stride per stage) ----
    const float* aptr = A + (size_t)(row0 + (tid >> 2)) * GEMM_K + (tid & 3) * 4;
    const int bn = tid & 255;                 // B tile n-row (0..255)
    const int bc0 = tid >> 8;                 // k'-group for it0 (0..1)
    const float* bptr0 = Bm + (size_t)bc0 * N + col0 + bn;
    const float* bptr1 = bptr0 + (size_t)2 * N;     // group bc0+2

    // ---- sts offsets (fixed) ----
    const int a_sw = (tid >> 3) & 3;                 // ((tid>>2)>>1)&3
    const int aoff = (tid >> 2) * 16 + (tid & 3);
    const int b_sw = (bn >> 1) & 3;
    const int boff0 = bn * 16 + ((bc0 ^ b_sw) << 2);
    const int boff1 = bn * 16 + (((bc0 + 2) ^ b_sw) << 2);

    // ---- fragment base offsets (swizzle group invariant across mf/nf) ----
    const int ra_base = wm * 32 + gid;
    const int aFragBase = ra_base * 16 + ((tig ^ ((ra_base >> 1) & 3)) << 2);
    const int nb = wn * 64 + gid;
    const int bFragBase = nb * 16 + ((tig ^ ((nb >> 1) & 3)) << 2);

    float acc[2][8][4];
#pragma unroll
    for (int mf = 0; mf < 2; mf++)
#pragma unroll
        for (int nf = 0; nf < 8; nf++)
#pragma unroll
            for (int i = 0; i < 4; i++) acc[mf][nf][i] = 0.0f;

    float4 ra;
    float rb0[4], rb1[4];

    auto ldg = [&]() {
        ra = *reinterpret_cast<const float4*>(aptr);
        aptr += GKS;
#pragma unroll
        for (int jj = 0; jj < 4; jj++) {
            rb0[jj] = bptr0[(size_t)(jj * 4) * N];
            rb1[jj] = bptr1[(size_t)(jj * 4) * N];
        }
        bptr0 += (size_t)GKS * N;
        bptr1 += (size_t)GKS * N;
    };

    auto sts = [&](float* As_, float* Bs_) {
        // A: element jj of float4 has k = at4*4+jj -> k' group jj, offset at4
        As_[aoff + ((0 ^ a_sw) << 2)] = __uint_as_float(to_tf32(ra.x));
        As_[aoff + ((1 ^ a_sw) << 2)] = __uint_as_float(to_tf32(ra.y));
        As_[aoff + ((2 ^ a_sw) << 2)] = __uint_as_float(to_tf32(ra.z));
        As_[aoff + ((3 ^ a_sw) << 2)] = __uint_as_float(to_tf32(ra.w));
        uint4 t0, t1;
        t0.x = to_tf32(rb0[0]); t0.y = to_tf32(rb0[1]);
        t0.z = to_tf32(rb0[2]); t0.w = to_tf32(rb0[3]);
        t1.x = to_tf32(rb1[0]); t1.y = to_tf32(rb1[1]);
        t1.z = to_tf32(rb1[2]); t1.w = to_tf32(rb1[3]);
        *reinterpret_cast<uint4*>(&Bs_[boff0]) = t0;
        *reinterpret_cast<uint4*>(&Bs_[boff1]) = t1;
    };

    auto compute = [&](const float* As_, const float* Bs_) {
        float4 av0[2], av1[2];
#pragma unroll
        for (int mf = 0; mf < 2; mf++) {
            av0[mf] = *reinterpret_cast<const float4*>(&As_[aFragBase + 256 * mf]);
            av1[mf] = *reinterpret_cast<const float4*>(&As_[aFragBase + 256 * mf + 128]);
        }
#pragma unroll
        for (int nf = 0; nf < 8; nf++) {
            float4 bv = *reinterpret_cast<const float4*>(&Bs_[bFragBase + 128 * nf]);
#pragma unroll
            for (int mf = 0; mf < 2; mf++) {
                mma_tf32(acc[mf][nf],
                         __float_as_uint(av0[mf].x), __float_as_uint(av1[mf].x),
                         __float_as_uint(av0[mf].y), __float_as_uint(av1[mf].y),
                         __float_as_uint(bv.x), __float_as_uint(bv.y));
                mma_tf32(acc[mf][nf],
                         __float_as_uint(av0[mf].z), __float_as_uint(av1[mf].z),
                         __float_as_uint(av0[mf].w), __float_as_uint(av1[mf].w),
                         __float_as_uint(bv.z), __float_as_uint(bv.w));
            }
        }
    };

    ldg();
    sts(As0, Bs0);
    __syncthreads();

#pragma unroll 2
    for (int kk = 0; kk < NSTAGE; kk++) {
        const float* As_ = (kk & 1) ? As1 : As0;
        const float* Bs_ = (kk & 1) ? Bs1 : Bs0;
        if (kk + 1 < NSTAGE) ldg();
        compute(As_, Bs_);
        if (kk + 1 < NSTAGE) {
            sts((kk & 1) ? As0 : As1, (kk & 1) ? Bs0 : Bs1);
            __syncthreads();
        }
    }

    // Epilogue: c0,c1 = (r, 2*tig), (r, 2*tig+1); c2,c3 = same at r+8
#pragma unroll
    for (int mf = 0; mf < 2; mf++) {
#pragma unroll
        for (int nf = 0; nf < 8; nf++) {
            int r = row0 + wm * 32 + mf * 16 + gid;
            int c = col0 + wn * 64 + nf * 8 + tig * 2;
            float2 lo = make_float2(acc[mf][nf][0], acc[mf][nf][1]);
            float2 hi = make_float2(acc[mf][nf][2], acc[mf][nf][3]);
            *reinterpret_cast<float2*>(&C[(size_t)r * N + c]) = lo;
            *reinterpret_cast<float2*>(&C[(size_t)(r + 8) * N + c]) = hi;
        }
    }
}

// ===========================================================================
// Flash attention via mma.sync tf32 (causal). Unchanged from round 9 (passes).
// ===========================================================================
#define ATS 68   // smem row stride (floats)

__global__ __launch_bounds__(256, 1)
void flash_attn_mma(const float* __restrict__ qkv, float* __restrict__ y) {
    extern __shared__ float sm[];
    float* Ks = sm;                  // [64][68]
    float* Vs = sm + 64 * ATS;       // [64][68]
    float* Ps = sm + 2 * 64 * ATS;   // [128][68] (also Q staging)

    const int tid = threadIdx.x;
    const int lane = tid & 31;
    const int w = tid >> 5;          // 0..7
    const int gid = lane >> 2;       // 0..7
    const int tig = lane & 3;        // 0..3
    const int bh = blockIdx.x;
    const int b = bh >> 4;
    const int h = bh & 15;
    const int q0 = (15 - (int)blockIdx.y) * 128;   // heavy blocks first
    const int row3 = 3 * DD;

    const float* qkv_b = qkv + (size_t)(b * TT) * row3;
    const float* qgm = qkv_b + h * HD;
    const float* kgm = qkv_b + DD + h * HD;
    const float* vgm = qkv_b + 2 * DD + h * HD;

    // ---- Stage Q tile into Ps, then build per-warp Q fragments (2x split) --
#pragma unroll
    for (int i = 0; i < 8; i++) {
        int idx = tid + i * 256;
        int r = idx >> 4, c4 = idx & 15;
        float4 v = *reinterpret_cast<const float4*>(
            qgm + (size_t)(q0 + r) * row3 + c4 * 4);
        *reinterpret_cast<float4*>(Ps + r * ATS + c4 * 4) = v;
    }
    __syncthreads();

    const float scale2 = 0.125f * 1.4426950408889634f;
    uint32_t qhi[8][4], qlo[8][4];
    {
        const int r0 = w * 16 + gid;
#pragma unroll
        for (int c = 0; c < 8; c++) {
            float v0 = Ps[r0 * ATS + 8 * c + tig] * scale2;          // a0
            float v1 = Ps[(r0 + 8) * ATS + 8 * c + tig] * scale2;    // a1
            float v2 = Ps[r0 * ATS + 8 * c + tig + 4] * scale2;      // a2
            float v3 = Ps[(r0 + 8) * ATS + 8 * c + tig + 4] * scale2;// a3
            qhi[c][0] = to_tf32(v0); qlo[c][0] = to_tf32(v0 - __uint_as_float(qhi[c][0]));
            qhi[c][1] = to_tf32(v1); qlo[c][1] = to_tf32(v1 - __uint_as_float(qhi[c][1]));
            qhi[c][2] = to_tf32(v2); qlo[c][2] = to_tf32(v2 - __uint_as_float(qhi[c][2]));
            qhi[c][3] = to_tf32(v3); qlo[c][3] = to_tf32(v3 - __uint_as_float(qhi[c][3]));
        }
    }
    __syncthreads();

    float yacc[8][4];
#pragma unroll
    for (int j = 0; j < 8; j++)
#pragma unroll
        for (int e = 0; e < 4; e++) yacc[j][e] = 0.0f;
    float m0 = -1e30f, m1 = -1e30f, l0 = 0.0f, l1 = 0.0f;

    const int ntiles = q0 / 64 + 2;
    float4 kreg[4], vreg[4];

    auto ldg_kv = [&](int tn) {
        int kv0 = tn * 64;
#pragma unroll
        for (int i = 0; i < 4; i++) {
            int idx = tid + i * 256;
            int r = idx >> 4, c4 = idx & 15;
            kreg[i] = *reinterpret_cast<const float4*>(
                kgm + (size_t)(kv0 + r) * row3 + c4 * 4);
            vreg[i] = *reinterpret_cast<const float4*>(
                vgm + (size_t)(kv0 + r) * row3 + c4 * 4);
        }
    };
    auto sts_kv = [&]() {
#pragma unroll
        for (int i = 0; i < 4; i++) {
            int idx = tid + i * 256;
            int r = idx >> 4, c4 = idx & 15;
            uint4 tk, tv;
            tk.x = to_tf32(kreg[i].x); tk.y = to_tf32(kreg[i].y);
            tk.z = to_tf32(kreg[i].z); tk.w = to_tf32(kreg[i].w);
            tv.x = to_tf32(vreg[i].x); tv.y = to_tf32(vreg[i].y);
            tv.z = to_tf32(vreg[i].z); tv.w = to_tf32(vreg[i].w);
            *reinterpret_cast<uint4*>(Ks + r * ATS + c4 * 4) = tk;
            *reinterpret_cast<uint4*>(Vs + r * ATS + c4 * 4) = tv;
        }
    };

    ldg_kv(0);
    sts_kv();
    __syncthreads();

    const int pr0 = (w * 16 + gid) * ATS;

    for (int t = 0; t < ntiles; t++) {
        const int kv0 = t * 64;
        if (t + 1 < ntiles) ldg_kv(t + 1);

        const bool active = (kv0 <= q0 + w * 16 + 15);
        if (active) {
            // ---- QK^T (2xTF32: q_hi*K + q_lo*K) ----
            float sacc[8][4];
#pragma unroll
            for (int j = 0; j < 8; j++)
#pragma unroll
                for (int e = 0; e < 4; e++) sacc[j][e] = 0.0f;
#pragma unroll
            for (int j = 0; j < 8; j++) {
                const int kr = (8 * j + gid) * ATS;
#pragma unroll
                for (int c = 0; c < 8; c++) {
                    uint32_t b0 = __float_as_uint(Ks[kr + 8 * c + tig]);
                    uint32_t b1 = __float_as_uint(Ks[kr + 8 * c + tig + 4]);
                    mma_tf32(sacc[j], qhi[c][0], qhi[c][1], qhi[c][2], qhi[c][3], b0, b1);
                    mma_tf32(sacc[j], qlo[c][0], qlo[c][1], qlo[c][2], qlo[c][3], b0, b1);
                }
            }

            // ---- causal mask (only last two tiles) ----
            if (t >= ntiles - 2) {
                const int r0g = q0 + w * 16 + gid;
#pragma unroll
                for (int j = 0; j < 8; j++) {
                    int col = kv0 + 8 * j + 2 * tig;
                    if (col > r0g)         sacc[j][0] = -1e30f;
                    if (col + 1 > r0g)     sacc[j][1] = -1e30f;
                    if (col > r0g + 8)     sacc[j][2] = -1e30f;
                    if (col + 1 > r0g + 8) sacc[j][3] = -1e30f;
                }
            }

            // ---- online softmax ----
            float mt0 = -1e30f, mt1 = -1e30f;
#pragma unroll
            for (int j = 0; j < 8; j++) {
                mt0 = fmaxf(mt0, fmaxf(sacc[j][0], sacc[j][1]));
                mt1 = fmaxf(mt1, fmaxf(sacc[j][2], sacc[j][3]));
            }
            mt0 = fmaxf(mt0, __shfl_xor_sync(0xffffffffu, mt0, 1));
            mt0 = fmaxf(mt0, __shfl_xor_sync(0xffffffffu, mt0, 2));
            mt1 = fmaxf(mt1, __shfl_xor_sync(0xffffffffu, mt1, 1));
            mt1 = fmaxf(mt1, __shfl_xor_sync(0xffffffffu, mt1, 2));

            float mn0 = fmaxf(m0, mt0), mn1 = fmaxf(m1, mt1);
            float cr0 = fast_exp2(m0 - mn0), cr1 = fast_exp2(m1 - mn1);
            m0 = mn0; m1 = mn1;
#pragma unroll
            for (int j = 0; j < 8; j++) {
                yacc[j][0] *= cr0; yacc[j][1] *= cr0;
                yacc[j][2] *= cr1; yacc[j][3] *= cr1;
            }

            float rs0 = 0.0f, rs1 = 0.0f;
#pragma unroll
            for (int j = 0; j < 8; j++) {
                float p0 = fast_exp2(sacc[j][0] - m0);
                float p1 = fast_exp2(sacc[j][1] - m0);
                float p2 = fast_exp2(sacc[j][2] - m1);
                float p3 = fast_exp2(sacc[j][3] - m1);
                rs0 += p0 + p1; rs1 += p2 + p3;
                float2 lo, hi;
                lo.x = __uint_as_float(to_tf32(p0)); lo.y = __uint_as_float(to_tf32(p1));
                hi.x = __uint_as_float(to_tf32(p2)); hi.y = __uint_as_float(to_tf32(p3));
                *reinterpret_cast<float2*>(Ps + pr0 + 8 * j + 2 * tig) = lo;
                *reinterpret_cast<float2*>(Ps + pr0 + 8 * ATS + 8 * j + 2 * tig) = hi;
            }
            rs0 += __shfl_xor_sync(0xffffffffu, rs0, 1);
            rs0 += __shfl_xor_sync(0xffffffffu, rs0, 2);
            rs1 += __shfl_xor_sync(0xffffffffu, rs1, 1);
            rs1 += __shfl_xor_sync(0xffffffffu, rs1, 2);
            l0 = l0 * cr0 + rs0;
            l1 = l1 * cr1 + rs1;

            __syncwarp();

            // ---- P @ V ----
#pragma unroll
            for (int c = 0; c < 8; c++) {
                uint32_t a0 = __float_as_uint(Ps[pr0 + 8 * c + tig]);
                uint32_t a1 = __float_as_uint(Ps[pr0 + 8 * ATS + 8 * c + tig]);
                uint32_t a2 = __float_as_uint(Ps[pr0 + 8 * c + tig + 4]);
                uint32_t a3 = __float_as_uint(Ps[pr0 + 8 * ATS + 8 * c + tig + 4]);
                const int vr = (8 * c + tig) * ATS;
#pragma unroll
                for (int j = 0; j < 8; j++) {
                    uint32_t b0 = __float_as_uint(Vs[vr + 8 * j + gid]);
                    uint32_t b1 = __float_as_uint(Vs[vr + 4 * ATS + 8 * j + gid]);
                    mma_tf32(yacc[j], a0, a1, a2, a3, b0, b1);
                }
            }
        }

        __syncthreads();                 // all warps done with Ks/Vs
        if (t + 1 < ntiles) {
            sts_kv();
            __syncthreads();             // tiles visible before next compute
        }
    }

    // ---- epilogue: normalize, store ----
    const float inv0 = 1.0f / l0;
    const float inv1 = 1.0f / l1;
    const int r0 = q0 + w * 16 + gid;
#pragma unroll
    for (int j = 0; j < 8; j++) {
        int col = h * HD + 8 * j + 2 * tig;
        float2 lo = make_float2(yacc[j][0] * inv0, yacc[j][1] * inv0);
        float2 hi = make_float2(yacc[j][2] * inv1, yacc[j][3] * inv1);
        *reinterpret_cast<float2*>(y + (size_t)(b * TT + r0) * DD + col) = lo;
        *reinterpret_cast<float2*>(y + (size_t)(b * TT + r0 + 8) * DD + col) = hi;
    }
}

// ---------------------------------------------------------------------------
// kernel_launch
// ---------------------------------------------------------------------------
extern "C" void kernel_launch(void* const* d_in, const int* in_sizes, int n_in,
                              void* d_out, int out_size) {
    const float* x  = (const float*)d_in[0];   // [4,2048,1024]
    const float* Wa = (const float*)d_in[1];   // [1024,3072]
    const float* Wp = (const float*)d_in[2];   // [1024,1024]
    float* out = (float*)d_out;                // [4,2048,1024]

    float* qkv_ptr = nullptr;
    float* y_ptr = nullptr;
    cudaGetSymbolAddress((void**)&qkv_ptr, g_qkv);
    cudaGetSymbolAddress((void**)&y_ptr, g_y);

    const int M = BB * TT;                     // 8192

    cudaFuncSetAttribute(mma_gemm, cudaFuncAttributeMaxDynamicSharedMemorySize,
                         GEMM_SMEM);

    // 1) QKV GEMM: [8192,1024] @ [1024,3072] -> g_qkv   (mma.sync tf32)
    {
        dim3 grid(3 * DD / 256, M / 128);
        mma_gemm<<<grid, 512, GEMM_SMEM>>>(x, Wa, qkv_ptr, 3 * DD);
    }

    // 2) Flash attention (mma.sync tf32) -> g_y
    {
        const int smem_bytes = (2 * 64 * ATS + 128 * ATS) * (int)sizeof(float); // 69632
        cudaFuncSetAttribute(flash_attn_mma,
                             cudaFuncAttributeMaxDynamicSharedMemorySize, smem_bytes);
        dim3 grid(BB * HH, TT / 128);
        flash_attn_mma<<<grid, 256, smem_bytes>>>(qkv_ptr, y_ptr);
    }

    // 3) Proj GEMM: [8192,1024] @ [1024,1024] -> out    (mma.sync tf32)
    {
        dim3 grid(DD / 256, M / 128);
        mma_gemm<<<grid, 512, GEMM_SMEM>>>(y_ptr, Wp, out, DD);
    }
}